// round 9
// baseline (speedup 1.0000x reference)
#include <cuda_runtime.h>
#include <cstdint>

#define Hh   181
#define KK   92           // k-pairs: covers k=0..183 (zeros beyond 180)
#define KKP  (KK + 4)     // padded for prefetch ring (extra rows stay zero)
#define Tt   1024
#define ROWS 8
#define NBLK 128
#define NTHR 384
#define PF   4            // weight prefetch distance (kk units)

// Packed pair weights: [kk*Hh + j]
//   g_wA = (wr[2kk], wr[2kk+1], wz[2kk], wz[2kk+1])
//   g_wN = (wn[2kk], wn[2kk+1])
__device__ __align__(16) float4 g_wA[KKP * Hh];   // zero-init pad rows
__device__ __align__(16) float2 g_wN[KKP * Hh];

// packed f32x2 FMA: acc = a*b + acc (two independent fp32 lanes)
#define FMA2(acc, a, b) \
    asm("fma.rn.f32x2 %0, %1, %2, %0;" : "+l"(acc) : "l"(a), "l"(b))

__device__ __forceinline__ float hsum2(unsigned long long v) {
    float lo = __uint_as_float((unsigned)(v & 0xFFFFFFFFull));
    float hi = __uint_as_float((unsigned)(v >> 32));
    return lo + hi;
}
// L2-only (no L1 allocation) 16B / 8B loads
__device__ __forceinline__ ulonglong2 ldcg16(const void* p) {
    ulonglong2 r;
    asm("ld.global.cg.v2.u64 {%0,%1}, [%2];" : "=l"(r.x), "=l"(r.y) : "l"(p));
    return r;
}
__device__ __forceinline__ unsigned long long ldcg8(const void* p) {
    unsigned long long r;
    asm("ld.global.cg.u64 %0, [%1];" : "=l"(r) : "l"(p));
    return r;
}

__global__ void prep_w_kernel(const float* __restrict__ w_hh) {
    int idx = blockIdx.x * blockDim.x + threadIdx.x;
    if (idx >= KK * Hh) return;
    int kk = idx / Hh, j = idx % Hh;
    int k0 = 2 * kk, k1 = 2 * kk + 1;
    float r0 = w_hh[j * Hh + k0];
    float r1 = (k1 < Hh) ? w_hh[j * Hh + k1] : 0.f;
    float z0 = w_hh[(Hh + j) * Hh + k0];
    float z1 = (k1 < Hh) ? w_hh[(Hh + j) * Hh + k1] : 0.f;
    float n0 = w_hh[(2 * Hh + j) * Hh + k0];
    float n1 = (k1 < Hh) ? w_hh[(2 * Hh + j) * Hh + k1] : 0.f;
    if (k0 >= Hh) { r0 = z0 = n0 = 0.f; }
    g_wA[idx] = make_float4(r0, r1, z0, z1);
    g_wN[idx] = make_float2(n0, n1);
}

__global__ __launch_bounds__(NTHR, 1) void gru_kernel(
    const float* __restrict__ x,
    const float* __restrict__ w_ih,
    const float* __restrict__ b_ih,
    const float* __restrict__ b_hh,
    const float* __restrict__ w_fc,
    const float* __restrict__ b_fc,
    float* __restrict__ out)
{
    __shared__ __align__(16) float xs[Tt][ROWS];           // 32 KB
    __shared__ __align__(16) float2 hT2[2][KK][ROWS];      // 11.5 KB double-buffered

    const int tid = threadIdx.x;
    const int blk = blockIdx.x;

    for (int i = tid; i < ROWS * Tt; i += NTHR) {
        int r = i / Tt, t = i % Tt;
        xs[t][r] = x[(blk * ROWS + r) * Tt + t];
    }
    for (int i = tid; i < 2 * KK * ROWS * 2; i += NTHR)
        ((float*)hT2)[i] = 0.f;

    // Thread pair (2j, 2j+1) shares gate j; even -> rows 0..3, odd -> rows 4..7.
    const int  j   = tid >> 1;
    const int  hi  = tid & 1;
    const bool act = (j < Hh);
    const int  jj  = act ? j : 0;
    const int  rb  = hi * 4;

    float wihR = 0.f, wihZ = 0.f, wihN = 0.f;
    float bR = 0.f, bZ = 0.f, bihN = 0.f, bhhN = 0.f;
    if (act) {
        wihR = w_ih[j]; wihZ = w_ih[Hh + j]; wihN = w_ih[2 * Hh + j];
        bR   = b_ih[j]          + b_hh[j];
        bZ   = b_ih[Hh + j]     + b_hh[Hh + j];
        bihN = b_ih[2 * Hh + j];
        bhhN = b_hh[2 * Hh + j];
    }
    float hprev[4] = {0.f, 0.f, 0.f, 0.f};

    const char* pWA = (const char*)&g_wA[jj];
    const char* pWN = (const char*)&g_wN[jj];
    const int strA = Hh * 16, strN = Hh * 8;

    __syncthreads();

    int cur = 0;
    for (int t = 0; t < Tt; ++t) {
        unsigned long long aR[4] = {0,0,0,0};
        unsigned long long aZ[4] = {0,0,0,0};
        unsigned long long aN[4] = {0,0,0,0};

        // prefetch ring, distance PF=4 (padded arrays: kk+PF always readable)
        ulonglong2 wbuf[PF]; unsigned long long nbuf[PF];
        #pragma unroll
        for (int s = 0; s < PF; ++s) {
            wbuf[s] = ldcg16(pWA + s * strA);
            nbuf[s] = ldcg8 (pWN + s * strN);
        }

        const float2 (*hb)[ROWS] = hT2[cur];
        #pragma unroll 4
        for (int kk = 0; kk < KK; ++kk) {
            const int slot = kk & (PF - 1);
            ulonglong2 w1 = wbuf[slot];
            unsigned long long wn2 = nbuf[slot];
            wbuf[slot] = ldcg16(pWA + (kk + PF) * strA);
            nbuf[slot] = ldcg8 (pWN + (kk + PF) * strN);
            ulonglong2 hA = *(const ulonglong2*)&hb[kk][rb];
            ulonglong2 hB = *(const ulonglong2*)&hb[kk][rb + 2];
            FMA2(aR[0], w1.x, hA.x); FMA2(aR[1], w1.x, hA.y);
            FMA2(aR[2], w1.x, hB.x); FMA2(aR[3], w1.x, hB.y);
            FMA2(aZ[0], w1.y, hA.x); FMA2(aZ[1], w1.y, hA.y);
            FMA2(aZ[2], w1.y, hB.x); FMA2(aZ[3], w1.y, hB.y);
            FMA2(aN[0], wn2,  hA.x); FMA2(aN[1], wn2,  hA.y);
            FMA2(aN[2], wn2,  hB.x); FMA2(aN[3], wn2,  hB.y);
        }

        // epilogue: thread-local accumulators -> write OTHER buffer (no WAR barrier)
        if (act) {
            float4 xv = *(const float4*)&xs[t][rb];
            float xr[4] = {xv.x, xv.y, xv.z, xv.w};
            float hn[4];
            #pragma unroll
            for (int r = 0; r < 4; ++r) {
                float pr = hsum2(aR[r]) + xr[r] * wihR + bR;
                float rg = __fdividef(1.f, 1.f + __expf(-pr));
                float pz = hsum2(aZ[r]) + xr[r] * wihZ + bZ;
                float zg = __fdividef(1.f, 1.f + __expf(-pz));
                float pn = xr[r] * wihN + bihN + rg * (hsum2(aN[r]) + bhhN);
                float e2 = __expf(-2.f * fabsf(pn));
                float th = copysignf(__fdividef(1.f - e2, 1.f + e2), pn);
                hn[r] = (1.f - zg) * th + zg * hprev[r];
                hprev[r] = hn[r];
            }
            float* hw = (float*)hT2[cur ^ 1] + (j >> 1) * (ROWS * 2) + (j & 1);
            hw[(rb + 0) * 2] = hn[0];
            hw[(rb + 1) * 2] = hn[1];
            hw[(rb + 2) * 2] = hn[2];
            hw[(rb + 3) * 2] = hn[3];
        }
        __syncthreads();   // single barrier: h_new visible before next step
        cur ^= 1;
    }

    // After 1024 steps cur==0; final h lives in hT2[0].
    if (tid < ROWS * 10) {
        int r = tid / 10, c = tid % 10;
        float s = b_fc[c];
        const float* hb = (const float*)hT2[0];
        #pragma unroll 4
        for (int k = 0; k < Hh; ++k)
            s += hb[(k >> 1) * (ROWS * 2) + r * 2 + (k & 1)] * __ldg(&w_fc[c * Hh + k]);
        out[(blk * ROWS + r) * 10 + c] = s;
    }
}

extern "C" void kernel_launch(void* const* d_in, const int* in_sizes, int n_in,
                              void* d_out, int out_size) {
    const float* x    = (const float*)d_in[0];
    const float* w_ih = (const float*)d_in[1];
    const float* w_hh = (const float*)d_in[2];
    const float* b_ih = (const float*)d_in[3];
    const float* b_hh = (const float*)d_in[4];
    const float* w_fc = (const float*)d_in[5];
    const float* b_fc = (const float*)d_in[6];

    prep_w_kernel<<<(KK * Hh + 255) / 256, 256>>>(w_hh);
    gru_kernel<<<NBLK, NTHR>>>(x, w_ih, b_ih, b_hh, w_fc, b_fc, (float*)d_out);
}

// round 11
// speedup vs baseline: 1.5604x; 1.5604x over previous
#include <cuda_runtime.h>
#include <cstdint>

#define Hh   181
#define KK   92           // k-pairs: covers k=0..183 (zeros beyond 180)
#define PF   4            // weight prefetch distance (kk units)
#define KKP  (KK + PF)    // padded: ring reads kk+PF; pad rows stay zero
#define Tt   1024
#define ROWS 8
#define NBLK 128
#define NTHR 384

// Packed pair weights: [kk*Hh + j]
//   g_wA = (wr[2kk], wr[2kk+1], wz[2kk], wz[2kk+1])
//   g_wN = (wn[2kk], wn[2kk+1])
__device__ __align__(16) float4 g_wA[KKP * Hh];   // zero-init pad rows
__device__ __align__(16) float2 g_wN[KKP * Hh];

// packed f32x2 FMA: acc = a*b + acc (two independent fp32 lanes)
#define FMA2(acc, a, b) \
    asm("fma.rn.f32x2 %0, %1, %2, %0;" : "+l"(acc) : "l"(a), "l"(b))

__device__ __forceinline__ float hsum2(unsigned long long v) {
    float lo = __uint_as_float((unsigned)(v & 0xFFFFFFFFull));
    float hi = __uint_as_float((unsigned)(v >> 32));
    return lo + hi;
}

__global__ void prep_w_kernel(const float* __restrict__ w_hh) {
    int idx = blockIdx.x * blockDim.x + threadIdx.x;
    if (idx >= KK * Hh) return;
    int kk = idx / Hh, j = idx % Hh;
    int k0 = 2 * kk, k1 = 2 * kk + 1;
    float r0 = w_hh[j * Hh + k0];
    float r1 = (k1 < Hh) ? w_hh[j * Hh + k1] : 0.f;
    float z0 = w_hh[(Hh + j) * Hh + k0];
    float z1 = (k1 < Hh) ? w_hh[(Hh + j) * Hh + k1] : 0.f;
    float n0 = w_hh[(2 * Hh + j) * Hh + k0];
    float n1 = (k1 < Hh) ? w_hh[(2 * Hh + j) * Hh + k1] : 0.f;
    if (k0 >= Hh) { r0 = z0 = n0 = 0.f; }
    g_wA[idx] = make_float4(r0, r1, z0, z1);
    g_wN[idx] = make_float2(n0, n1);
}

__global__ __launch_bounds__(NTHR, 1) void gru_kernel(
    const float* __restrict__ x,
    const float* __restrict__ w_ih,
    const float* __restrict__ b_ih,
    const float* __restrict__ b_hh,
    const float* __restrict__ w_fc,
    const float* __restrict__ b_fc,
    float* __restrict__ out)
{
    __shared__ __align__(16) float xs[Tt][ROWS];           // 32 KB
    __shared__ __align__(16) float2 hT2[2][KK][ROWS];      // 11.5 KB double-buffered

    const int tid = threadIdx.x;
    const int blk = blockIdx.x;

    for (int i = tid; i < ROWS * Tt; i += NTHR) {
        int r = i / Tt, t = i % Tt;
        xs[t][r] = x[(blk * ROWS + r) * Tt + t];
    }
    for (int i = tid; i < 2 * KK * ROWS * 2; i += NTHR)
        ((float*)hT2)[i] = 0.f;

    // Thread pair (2j, 2j+1) shares gate j; even -> rows 0..3, odd -> rows 4..7.
    const int  j   = tid >> 1;
    const int  hi  = tid & 1;
    const bool act = (j < Hh);
    const int  jj  = act ? j : 0;
    const int  rb  = hi * 4;

    float wihR = 0.f, wihZ = 0.f, wihN = 0.f;
    float bR = 0.f, bZ = 0.f, bihN = 0.f, bhhN = 0.f;
    if (act) {
        wihR = w_ih[j]; wihZ = w_ih[Hh + j]; wihN = w_ih[2 * Hh + j];
        bR   = b_ih[j]          + b_hh[j];
        bZ   = b_ih[Hh + j]     + b_hh[Hh + j];
        bihN = b_ih[2 * Hh + j];
        bhhN = b_hh[2 * Hh + j];
    }
    float hprev[4] = {0.f, 0.f, 0.f, 0.f};

    __syncthreads();

    int cur = 0;
    #pragma unroll 1
    for (int t = 0; t < Tt; ++t) {
        unsigned long long aR[4] = {0,0,0,0};
        unsigned long long aZ[4] = {0,0,0,0};
        unsigned long long aN[4] = {0,0,0,0};

        // Prefetch ring, distance PF=4, plain C loads (ptxas strength-reduces
        // the addressing; slot index is compile-time under unroll 4).
        ulonglong2 wbuf[PF]; unsigned long long nbuf[PF];
        #pragma unroll
        for (int s = 0; s < PF; ++s) {
            wbuf[s] = *(const ulonglong2*)&g_wA[s * Hh + jj];
            nbuf[s] = *(const unsigned long long*)&g_wN[s * Hh + jj];
        }

        const float2 (*hb)[ROWS] = hT2[cur];
        #pragma unroll 4
        for (int kk = 0; kk < KK; ++kk) {
            const int slot = kk & (PF - 1);
            ulonglong2 w1 = wbuf[slot];
            unsigned long long wn2 = nbuf[slot];
            wbuf[slot] = *(const ulonglong2*)&g_wA[(kk + PF) * Hh + jj];
            nbuf[slot] = *(const unsigned long long*)&g_wN[(kk + PF) * Hh + jj];
            ulonglong2 hA = *(const ulonglong2*)&hb[kk][rb];
            ulonglong2 hB = *(const ulonglong2*)&hb[kk][rb + 2];
            FMA2(aR[0], w1.x, hA.x); FMA2(aR[1], w1.x, hA.y);
            FMA2(aR[2], w1.x, hB.x); FMA2(aR[3], w1.x, hB.y);
            FMA2(aZ[0], w1.y, hA.x); FMA2(aZ[1], w1.y, hA.y);
            FMA2(aZ[2], w1.y, hB.x); FMA2(aZ[3], w1.y, hB.y);
            FMA2(aN[0], wn2,  hA.x); FMA2(aN[1], wn2,  hA.y);
            FMA2(aN[2], wn2,  hB.x); FMA2(aN[3], wn2,  hB.y);
        }

        // Epilogue on thread-local accumulators; write the OTHER buffer
        // (no WAR hazard), so only ONE barrier per step is needed.
        if (act) {
            float4 xv = *(const float4*)&xs[t][rb];
            float xr[4] = {xv.x, xv.y, xv.z, xv.w};
            float hn[4];
            #pragma unroll
            for (int r = 0; r < 4; ++r) {
                float pr = hsum2(aR[r]) + xr[r] * wihR + bR;
                float rg = __fdividef(1.f, 1.f + __expf(-pr));
                float pz = hsum2(aZ[r]) + xr[r] * wihZ + bZ;
                float zg = __fdividef(1.f, 1.f + __expf(-pz));
                float pn = xr[r] * wihN + bihN + rg * (hsum2(aN[r]) + bhhN);
                float e2 = __expf(-2.f * fabsf(pn));
                float th = copysignf(__fdividef(1.f - e2, 1.f + e2), pn);
                hn[r] = (1.f - zg) * th + zg * hprev[r];
                hprev[r] = hn[r];
            }
            float* hw = (float*)hT2[cur ^ 1] + (j >> 1) * (ROWS * 2) + (j & 1);
            hw[(rb + 0) * 2] = hn[0];
            hw[(rb + 1) * 2] = hn[1];
            hw[(rb + 2) * 2] = hn[2];
            hw[(rb + 3) * 2] = hn[3];
        }
        __syncthreads();   // h_new visible before next step
        cur ^= 1;
    }

    // After 1024 steps cur==0; final h lives in hT2[0].
    if (tid < ROWS * 10) {
        int r = tid / 10, c = tid % 10;
        float s = b_fc[c];
        const float* hb = (const float*)hT2[0];
        #pragma unroll 4
        for (int k = 0; k < Hh; ++k)
            s += hb[(k >> 1) * (ROWS * 2) + r * 2 + (k & 1)] * __ldg(&w_fc[c * Hh + k]);
        out[(blk * ROWS + r) * 10 + c] = s;
    }
}

extern "C" void kernel_launch(void* const* d_in, const int* in_sizes, int n_in,
                              void* d_out, int out_size) {
    const float* x    = (const float*)d_in[0];
    const float* w_ih = (const float*)d_in[1];
    const float* w_hh = (const float*)d_in[2];
    const float* b_ih = (const float*)d_in[3];
    const float* b_hh = (const float*)d_in[4];
    const float* w_fc = (const float*)d_in[5];
    const float* b_fc = (const float*)d_in[6];

    prep_w_kernel<<<(KK * Hh + 255) / 256, 256>>>(w_hh);
    gru_kernel<<<NBLK, NTHR>>>(x, w_ih, b_ih, b_hh, w_fc, b_fc, (float*)d_out);
}

// round 12
// speedup vs baseline: 1.6359x; 1.0483x over previous
#include <cuda_runtime.h>
#include <cstdint>

#define Hh   181
#define KK   92           // k-pairs: covers k=0..183 (zeros beyond 180)
#define KKP  (KK + 1)     // +1 pad row so distance-1 prefetch never branches
#define Tt   1024
#define ROWS 4
#define NBLK 256
#define NTHR 192

// Packed pair weights: [kk*Hh + j]
//   g_wA = (wr[2kk], wr[2kk+1], wz[2kk], wz[2kk+1])
//   g_wN = (wn[2kk], wn[2kk+1])
__device__ __align__(16) float4 g_wA[KKP * Hh];   // pad row stays zero
__device__ __align__(16) float2 g_wN[KKP * Hh];

// packed f32x2 FMA: acc = a*b + acc (two independent fp32 lanes)
#define FMA2(acc, a, b) \
    asm("fma.rn.f32x2 %0, %1, %2, %0;" : "+l"(acc) : "l"(a), "l"(b))

__device__ __forceinline__ float hsum2(unsigned long long v) {
    float lo = __uint_as_float((unsigned)(v & 0xFFFFFFFFull));
    float hi = __uint_as_float((unsigned)(v >> 32));
    return lo + hi;
}

__global__ void prep_w_kernel(const float* __restrict__ w_hh) {
    int idx = blockIdx.x * blockDim.x + threadIdx.x;
    if (idx >= KK * Hh) return;
    int kk = idx / Hh, j = idx % Hh;
    int k0 = 2 * kk, k1 = 2 * kk + 1;
    float r0 = w_hh[j * Hh + k0];
    float r1 = (k1 < Hh) ? w_hh[j * Hh + k1] : 0.f;
    float z0 = w_hh[(Hh + j) * Hh + k0];
    float z1 = (k1 < Hh) ? w_hh[(Hh + j) * Hh + k1] : 0.f;
    float n0 = w_hh[(2 * Hh + j) * Hh + k0];
    float n1 = (k1 < Hh) ? w_hh[(2 * Hh + j) * Hh + k1] : 0.f;
    if (k0 >= Hh) { r0 = z0 = n0 = 0.f; }
    g_wA[idx] = make_float4(r0, r1, z0, z1);
    g_wN[idx] = make_float2(n0, n1);
}

__global__ __launch_bounds__(NTHR, 2) void gru_kernel(
    const float* __restrict__ x,
    const float* __restrict__ w_ih,
    const float* __restrict__ b_ih,
    const float* __restrict__ b_hh,
    const float* __restrict__ w_fc,
    const float* __restrict__ b_fc,
    float* __restrict__ out)
{
    __shared__ __align__(16) float xs[Tt][ROWS];           // 16 KB
    __shared__ __align__(16) float2 hT2[2][KK][ROWS];      // 5.75 KB double-buffered

    const int tid = threadIdx.x;
    const int blk = blockIdx.x;

    for (int i = tid; i < ROWS * Tt; i += NTHR) {
        int r = i / Tt, t = i % Tt;
        xs[t][r] = x[(blk * ROWS + r) * Tt + t];
    }
    for (int i = tid; i < 2 * KK * ROWS * 2; i += NTHR)
        ((float*)hT2)[i] = 0.f;

    // One thread per gate j, handling all 4 rows.
    const int  j   = tid;
    const bool act = (j < Hh);
    const int  jj  = act ? j : 0;

    float wihR = 0.f, wihZ = 0.f, wihN = 0.f;
    float bR = 0.f, bZ = 0.f, bihN = 0.f, bhhN = 0.f;
    if (act) {
        wihR = w_ih[j]; wihZ = w_ih[Hh + j]; wihN = w_ih[2 * Hh + j];
        bR   = b_ih[j]          + b_hh[j];
        bZ   = b_ih[Hh + j]     + b_hh[Hh + j];
        bihN = b_ih[2 * Hh + j];
        bhhN = b_hh[2 * Hh + j];
    }
    float hprev[4] = {0.f, 0.f, 0.f, 0.f};

    __syncthreads();

    int cur = 0;
    #pragma unroll 1
    for (int t = 0; t < Tt; ++t) {
        unsigned long long aR[4] = {0,0,0,0};
        unsigned long long aZ[4] = {0,0,0,0};
        unsigned long long aN[4] = {0,0,0,0};

        // Distance-1 prefetch (R8 style; pad row makes kk+1 always loadable).
        ulonglong2 w1 = *(const ulonglong2*)&g_wA[jj];
        unsigned long long wn2 = *(const unsigned long long*)&g_wN[jj];

        const float2 (*hb)[ROWS] = hT2[cur];
        #pragma unroll 4
        for (int kk = 0; kk < KK; ++kk) {
            ulonglong2 w1n = *(const ulonglong2*)&g_wA[(kk + 1) * Hh + jj];
            unsigned long long wn2n = *(const unsigned long long*)&g_wN[(kk + 1) * Hh + jj];
            ulonglong2 hA = *(const ulonglong2*)&hb[kk][0];
            ulonglong2 hB = *(const ulonglong2*)&hb[kk][2];
            FMA2(aR[0], w1.x, hA.x); FMA2(aR[1], w1.x, hA.y);
            FMA2(aR[2], w1.x, hB.x); FMA2(aR[3], w1.x, hB.y);
            FMA2(aZ[0], w1.y, hA.x); FMA2(aZ[1], w1.y, hA.y);
            FMA2(aZ[2], w1.y, hB.x); FMA2(aZ[3], w1.y, hB.y);
            FMA2(aN[0], wn2,  hA.x); FMA2(aN[1], wn2,  hA.y);
            FMA2(aN[2], wn2,  hB.x); FMA2(aN[3], wn2,  hB.y);
            w1 = w1n; wn2 = wn2n;
        }

        // Epilogue on thread-local accumulators; write the OTHER buffer
        // (no WAR hazard) -> ONE barrier per step.
        if (act) {
            float4 xv = *(const float4*)&xs[t][0];
            float xr[4] = {xv.x, xv.y, xv.z, xv.w};
            float hn[4];
            #pragma unroll
            for (int r = 0; r < 4; ++r) {
                float pr = hsum2(aR[r]) + xr[r] * wihR + bR;
                float rg = __fdividef(1.f, 1.f + __expf(-pr));
                float pz = hsum2(aZ[r]) + xr[r] * wihZ + bZ;
                float zg = __fdividef(1.f, 1.f + __expf(-pz));
                float pn = xr[r] * wihN + bihN + rg * (hsum2(aN[r]) + bhhN);
                float e2 = __expf(-2.f * fabsf(pn));
                float th = copysignf(__fdividef(1.f - e2, 1.f + e2), pn);
                hn[r] = (1.f - zg) * th + zg * hprev[r];
                hprev[r] = hn[r];
            }
            // scatter into pair layout: component (j&1) of hT2[j>>1][row]
            float* hw = (float*)hT2[cur ^ 1] + (j >> 1) * (ROWS * 2) + (j & 1);
            hw[0 * 2] = hn[0];
            hw[1 * 2] = hn[1];
            hw[2 * 2] = hn[2];
            hw[3 * 2] = hn[3];
        }
        __syncthreads();   // h_new visible before next step
        cur ^= 1;
    }

    // After 1024 steps cur==0; final h lives in hT2[0].
    if (tid < ROWS * 10) {
        int r = tid / 10, c = tid % 10;
        float s = b_fc[c];
        const float* hb = (const float*)hT2[0];
        #pragma unroll 4
        for (int k = 0; k < Hh; ++k)
            s += hb[(k >> 1) * (ROWS * 2) + r * 2 + (k & 1)] * __ldg(&w_fc[c * Hh + k]);
        out[(blk * ROWS + r) * 10 + c] = s;
    }
}

extern "C" void kernel_launch(void* const* d_in, const int* in_sizes, int n_in,
                              void* d_out, int out_size) {
    const float* x    = (const float*)d_in[0];
    const float* w_ih = (const float*)d_in[1];
    const float* w_hh = (const float*)d_in[2];
    const float* b_ih = (const float*)d_in[3];
    const float* b_hh = (const float*)d_in[4];
    const float* w_fc = (const float*)d_in[5];
    const float* b_fc = (const float*)d_in[6];

    prep_w_kernel<<<(KK * Hh + 255) / 256, 256>>>(w_hh);
    gru_kernel<<<NBLK, NTHR>>>(x, w_ih, b_ih, b_hh, w_fc, b_fc, (float*)d_out);
}